// round 12
// baseline (speedup 1.0000x reference)
#include <cuda_runtime.h>
#include <cuda_bf16.h>
#include <math.h>
#include <stdint.h>

#define NB 2
#define NT 32
#define NI 2048
#define NF 64
#define TWOF 128
#define NL 5
#define NSPLIT 32
#define CHUNK 64
#define TM1 31
#define MP_STRIDE 264

#define RT_SIZE (NB*NI*TWOF)          // 524288
#define MT_OFF  RT_SIZE
#define LOSS_OFF (RT_SIZE + NB*TWOF)  // 524544

#define ES_STRIDE 68
#define ES_TILE   (32*ES_STRIDE)
#define SS_STRIDE 33

// ---------------- scratch (device globals: allocation-free, zero-init at load) ----
__device__ __nv_bfloat16 g_rh[NB*NT*NI*NF];   // r_hist scratch (bf16)
__device__ float g_eta[NB*NT*NI];
__device__ float g_W1T[TWOF*TWOF];            // sc_W1 transposed
__device__ unsigned char g_member[NT*NI];
__device__ int   g_cnt_pos[NB*TM1];           // self-zeroing (consumed+reset by tail)
__device__ int   g_cnt_neg[NB*TM1];
__device__ float g_mpart[NB*NT*NSPLIT*MP_STRIDE];
__device__ float g_a1[NB*NT];
__device__ float g_a2[NB*NT];
__device__ float g_sync[NB*TM1];
__device__ int   g_done_bt[NB*NT];            // self-zeroing
__device__ int   g_done_all;                  // self-zeroing

__device__ __forceinline__ float warp_sum(float v){
  #pragma unroll
  for (int o = 16; o > 0; o >>= 1) v += __shfl_xor_sync(0xffffffffu, v, o);
  return v;
}

__device__ __forceinline__ uint32_t f2tf32(float x){
  uint32_t r;
  asm("cvt.rna.tf32.f32 %0, %1;" : "=r"(r) : "f"(x));
  return r;
}

__device__ __forceinline__ void mma_tf32(float c[4], const uint32_t a[4],
                                         uint32_t b0, uint32_t b1){
  asm("mma.sync.aligned.m16n8k8.row.col.f32.tf32.tf32.f32 "
      "{%0,%1,%2,%3},{%4,%5,%6,%7},{%8,%9},{%0,%1,%2,%3};"
      : "+f"(c[0]), "+f"(c[1]), "+f"(c[2]), "+f"(c[3])
      : "r"(a[0]), "r"(a[1]), "r"(a[2]), "r"(a[3]), "r"(b0), "r"(b1));
}

// ---------------- K_main: main blocks (b<NB) + prep blocks (b==NB) ----------------
__global__ __launch_bounds__(256) void k_main(
    const float* __restrict__ e_seq, const float* __restrict__ Ws_w,
    const float* __restrict__ Ws_b, const float* __restrict__ w_eta,
    const int* __restrict__ close_idx_p, const float* __restrict__ Wiota,
    const int* __restrict__ perms, const float* __restrict__ sc_W1,
    float* __restrict__ d_out)
{
  __shared__ float smemA[64*ES_STRIDE];   // 17408B: Wsm -> Ks  (prep: transpose tile)
  __shared__ float Esf[2*ES_TILE];        // 17408B
  __shared__ float Ss[2*32*SS_STRIDE];    //  8448B
  __shared__ float ciS[2];

  int b = blockIdx.y;
  int tid = threadIdx.x;

  // ===== prep blocks: member scatter + W1T transpose =====
  if (b == NB){
    int bx = blockIdx.x;
    if (bx < NT){
      int t = bx;
      for (int j = tid; j < NI; j += 256){
        int p = perms[t*NI + j];
        g_member[t*NI + p] = (unsigned char)(j >= NI/2);
      }
    } else if (bx < NT + 16){
      int p = bx - NT;
      int r = p >> 2, cc = p & 3;
      float* tileT = smemA;   // [32][33]
      for (int x = tid; x < 1024; x += 256){
        int row = x >> 5, col = x & 31;
        tileT[col*33 + row] = sc_W1[(32*r + row)*TWOF + 32*cc + col];
      }
      __syncthreads();
      for (int x = tid; x < 1024; x += 256){
        int row = x >> 5, col = x & 31;
        g_W1T[(32*cc + row)*TWOF + 32*r + col] = tileT[row*33 + col];
      }
    }
    return;
  }

  // ===== main blocks =====
  int i0 = blockIdx.x * 2;
  int warp = tid >> 5, lane = tid & 31;
  int g  = lane >> 2, tg = lane & 3;

  float* Wsm = smemA;
  float* Ks  = smemA;

  if (warp < 2){
    const float4* wi = (const float4*)(Wiota + (size_t)(i0 + warp)*TWOF);
    const float4* wev = (const float4*)w_eta;
    float4 a = wi[lane], bv = wev[lane];
    float s = a.x*bv.x + a.y*bv.y + a.z*bv.z + a.w*bv.w;
    s = warp_sum(s);
    if (lane == 0) ciS[warp] = s;
  }

  {
    const float4* wg = (const float4*)Ws_w;
    #pragma unroll
    for (int x = tid; x < 1024; x += 256){
      int fo = x >> 4, c = x & 15;
      ((float4*)(Wsm + fo*ES_STRIDE))[c] = wg[x];
    }
  }
  {
    #pragma unroll
    for (int x = tid; x < 1024; x += 256){
      int tile = x >> 9, t = (x >> 4) & 31, c = x & 15;
      const float4* eg = (const float4*)(e_seq + ((size_t)b*NT*NI + (i0+tile))*NF);
      ((float4*)(Esf + (tile*32 + t)*ES_STRIDE))[c] = eg[(size_t)t*(NI*16) + c];
    }
  }
  __syncthreads();

  if (warp < 2 && lane < TM1){
    int cidx = *close_idx_p;
    const float* ef = Esf + warp*ES_TILE;
    float c0 = ef[lane*ES_STRIDE + cidx];
    float c1 = ef[(lane+1)*ES_STRIDE + cidx];
    float r = c1 / (c0 + 1e-8f);
    if (r > 1.0f)      atomicAdd(&g_cnt_pos[b*TM1 + lane], 1);
    else if (r < 1.0f) atomicAdd(&g_cnt_neg[b*TM1 + lane], 1);
  }

  // ---- k = e @ Ws^T + b via tf32 mma, hi/lo split ----
  float c[4][4];
  {
    int tl = warp >> 2, mt = (warp >> 1) & 1, nh = warp & 1;
    const float* Et = Esf + tl*ES_TILE + (mt*16)*ES_STRIDE;

    #pragma unroll
    for (int nt = 0; nt < 4; nt++)
      #pragma unroll
      for (int q = 0; q < 4; q++) c[nt][q] = 0.f;

    #pragma unroll
    for (int ks = 0; ks < 8; ks++){
      int k0 = ks*8;
      float af[4];
      af[0] = Et[g*ES_STRIDE + k0 + tg];
      af[1] = Et[(g+8)*ES_STRIDE + k0 + tg];
      af[2] = Et[g*ES_STRIDE + k0 + tg + 4];
      af[3] = Et[(g+8)*ES_STRIDE + k0 + tg + 4];
      uint32_t ah[4], al[4];
      #pragma unroll
      for (int q = 0; q < 4; q++){
        ah[q] = f2tf32(af[q]);
        al[q] = f2tf32(af[q] - __uint_as_float(ah[q]));
      }
      #pragma unroll
      for (int nt = 0; nt < 4; nt++){
        int n0 = nh*32 + nt*8;
        float b0f = Wsm[(n0+g)*ES_STRIDE + k0 + tg];
        float b1f = Wsm[(n0+g)*ES_STRIDE + k0 + tg + 4];
        uint32_t bh0 = f2tf32(b0f), bh1 = f2tf32(b1f);
        uint32_t bl0 = f2tf32(b0f - __uint_as_float(bh0));
        uint32_t bl1 = f2tf32(b1f - __uint_as_float(bh1));
        mma_tf32(c[nt], ah, bh0, bh1);
        mma_tf32(c[nt], ah, bl0, bl1);
        mma_tf32(c[nt], al, bh0, bh1);
      }
    }
  }
  __syncthreads();

  {
    int tl = warp >> 2, mt = (warp >> 1) & 1, nh = warp & 1;
    #pragma unroll
    for (int nt = 0; nt < 4; nt++){
      int n0 = nh*32 + nt*8;
      int col = n0 + 2*tg;
      float bb0 = __ldg(Ws_b + col), bb1 = __ldg(Ws_b + col + 1);
      int r0 = mt*16 + g;
      float* k0p = Ks + (tl*32 + r0)*ES_STRIDE + col;
      float* k1p = Ks + (tl*32 + r0 + 8)*ES_STRIDE + col;
      k0p[0] = c[nt][0] + bb0; k0p[1] = c[nt][1] + bb1;
      k1p[0] = c[nt][2] + bb0; k1p[1] = c[nt][3] + bb1;
    }
  }
  __syncthreads();

  // ---- scores S = (K K^T)/8 per tile ----
  {
    int stile = warp >> 2;
    int smt   = (warp >> 1) & 1;
    int snh   = warp & 1;
    const float* Km = Ks + (stile*32 + smt*16)*ES_STRIDE;
    const float* Kn = Ks + stile*32*ES_STRIDE;

    float sc[2][4];
    #pragma unroll
    for (int u = 0; u < 2; u++)
      #pragma unroll
      for (int q = 0; q < 4; q++) sc[u][q] = 0.f;

    #pragma unroll
    for (int ks = 0; ks < 8; ks++){
      int k0 = ks*8;
      float af[4];
      af[0] = Km[g*ES_STRIDE + k0 + tg];
      af[1] = Km[(g+8)*ES_STRIDE + k0 + tg];
      af[2] = Km[g*ES_STRIDE + k0 + tg + 4];
      af[3] = Km[(g+8)*ES_STRIDE + k0 + tg + 4];
      uint32_t ah[4], al[4];
      #pragma unroll
      for (int q = 0; q < 4; q++){
        ah[q] = f2tf32(af[q]);
        al[q] = f2tf32(af[q] - __uint_as_float(ah[q]));
      }
      #pragma unroll
      for (int u = 0; u < 2; u++){
        int n0 = (2*snh + u)*8;
        float b0f = Kn[(n0+g)*ES_STRIDE + k0 + tg];
        float b1f = Kn[(n0+g)*ES_STRIDE + k0 + tg + 4];
        uint32_t bh0 = f2tf32(b0f), bh1 = f2tf32(b1f);
        uint32_t bl0 = f2tf32(b0f - __uint_as_float(bh0));
        uint32_t bl1 = f2tf32(b1f - __uint_as_float(bh1));
        mma_tf32(sc[u], ah, bh0, bh1);
        mma_tf32(sc[u], ah, bl0, bl1);
        mma_tf32(sc[u], al, bh0, bh1);
      }
    }
    #pragma unroll
    for (int u = 0; u < 2; u++){
      int col = (2*snh + u)*8 + 2*tg;
      int r0 = smt*16 + g;
      float* s0 = Ss + (stile*32 + r0)*SS_STRIDE + col;
      float* s1 = Ss + (stile*32 + r0 + 8)*SS_STRIDE + col;
      s0[0] = sc[u][0]*0.125f; s0[1] = sc[u][1]*0.125f;
      s1[0] = sc[u][2]*0.125f; s1[1] = sc[u][3]*0.125f;
    }
  }
  __syncthreads();

  float we0 = __ldg(w_eta + lane),      we1 = __ldg(w_eta + 32 + lane);
  float we2 = __ldg(w_eta + 64 + lane), we3 = __ldg(w_eta + 96 + lane);

  #pragma unroll
  for (int tile = 0; tile < 2; tile++){
    int i = i0 + tile;
    float ci = ciS[tile];
    const float* Et = Esf + tile*ES_TILE;

    for (int tt = warp; tt < NT; tt += 8){
      const float* Srow = Ss + (tile*32 + tt)*SS_STRIDE;
      float s[NL];
      #pragma unroll
      for (int l = 0; l < NL; l++){
        int t2 = tt - 4 + l;
        s[l] = (t2 >= 0) ? Srow[t2] : -1e30f;
      }
      float mx = s[0];
      #pragma unroll
      for (int l = 1; l < NL; l++) mx = fmaxf(mx, s[l]);
      float pe[NL], psum = 0.f;
      #pragma unroll
      for (int l = 0; l < NL; l++){ pe[l] = expf(s[l] - mx); psum += pe[l]; }
      float inv = 1.0f / psum;
      float rh0 = 0.f, rh1 = 0.f;
      #pragma unroll
      for (int l = 0; l < NL; l++){
        int t2 = tt - 4 + l; if (t2 < 0) t2 = 0;
        float a = pe[l] * inv;
        rh0 += a * Et[t2*ES_STRIDE + lane];
        rh1 += a * Et[t2*ES_STRIDE + 32 + lane];
      }
      size_t rbase = (((size_t)b*NT + tt)*NI + i)*NF;
      g_rh[rbase + lane]      = __float2bfloat16(rh0);
      g_rh[rbase + 32 + lane] = __float2bfloat16(rh1);

      float e0 = Et[tt*ES_STRIDE + lane], e1 = Et[tt*ES_STRIDE + 32 + lane];
      float d = e0*we0 + e1*we1 + rh0*we2 + rh1*we3;
      d = warp_sum(d);
      float eta = fmaxf(d + ci, 0.f);
      if (lane == 0) g_eta[((size_t)b*NT + tt)*NI + i] = eta;

      if (tt == NT-1){
        float* ro = d_out + ((size_t)b*NI + i)*TWOF;
        ro[lane] = e0; ro[32+lane] = e1; ro[64+lane] = rh0; ro[96+lane] = rh1;
      }
    }
  }
}

// ---------------- K_msum + fused tail ----------------
__global__ __launch_bounds__(128) void k_msum(
    const float* __restrict__ e_seq,
    const float* __restrict__ w_M,
    const float* __restrict__ sc_b1,
    const float* __restrict__ sc_W2, const float* __restrict__ sc_b2,
    const float* __restrict__ b_M,
    float* __restrict__ d_out)
{
  int bt = blockIdx.x;
  int b = bt / NT, t = bt % NT;
  int s  = blockIdx.y;
  int tid = threadIdx.x;
  int warp = tid >> 5, lane = tid & 31;
  __shared__ float eta_s[CHUNK];
  __shared__ float w2_s[CHUNK];
  __shared__ float4 red[256];
  __shared__ int flags[2];
  float* redf = (float*)red;

  int i0 = s * CHUNK;
  if (tid < CHUNK){
    float e = g_eta[(size_t)bt*NI + i0 + tid];
    eta_s[tid] = e;
    w2_s[tid]  = g_member[t*NI + i0 + tid] ? e : 0.f;
  }
  __syncthreads();

  int fq = tid & 31;
  int jb = tid >> 5;
  bool hi = fq >= 16;
  int c = hi ? fq - 16 : fq;
  float4 a1 = make_float4(0.f,0.f,0.f,0.f);
  float4 a2 = make_float4(0.f,0.f,0.f,0.f);

  if (!hi){
    const float4* base = (const float4*)(e_seq + ((size_t)bt*NI + i0)*NF);
    #pragma unroll
    for (int j = jb; j < CHUNK; j += 4){
      float4 r = base[(size_t)j*16 + c];
      float w2 = w2_s[j], w1 = eta_s[j] - w2;
      a1.x += w1*r.x; a1.y += w1*r.y; a1.z += w1*r.z; a1.w += w1*r.w;
      a2.x += w2*r.x; a2.y += w2*r.y; a2.z += w2*r.z; a2.w += w2*r.w;
    }
  } else {
    const uint2* base = (const uint2*)(g_rh + ((size_t)bt*NI + i0)*NF);
    #pragma unroll
    for (int j = jb; j < CHUNK; j += 4){
      uint2 v = base[(size_t)j*16 + c];
      __nv_bfloat162 p0 = *(__nv_bfloat162*)&v.x;
      __nv_bfloat162 p1 = *(__nv_bfloat162*)&v.y;
      float4 r;
      r.x = __bfloat162float(p0.x); r.y = __bfloat162float(p0.y);
      r.z = __bfloat162float(p1.x); r.w = __bfloat162float(p1.y);
      float w2 = w2_s[j], w1 = eta_s[j] - w2;
      a1.x += w1*r.x; a1.y += w1*r.y; a1.z += w1*r.z; a1.w += w1*r.w;
      a2.x += w2*r.x; a2.y += w2*r.y; a2.z += w2*r.z; a2.w += w2*r.w;
    }
  }
  red[tid] = a1; red[128 + tid] = a2;
  __syncthreads();

  float* op = g_mpart + ((size_t)bt*NSPLIT + s)*MP_STRIDE;
  if (tid < 64){
    int which = tid >> 5;
    int q = tid & 31;
    float4 sum = red[which*128 + q];
    #pragma unroll
    for (int g2 = 1; g2 < 4; g2++){
      float4 v = red[which*128 + 32*g2 + q];
      sum.x += v.x; sum.y += v.y; sum.z += v.z; sum.w += v.w;
    }
    ((float4*)(op + which*TWOF))[q] = sum;
  } else if (tid < 96){
    int l = tid - 64;
    float d1 = 0.f, d2 = 0.f;
    #pragma unroll
    for (int j = l; j < CHUNK; j += 32){ float w2 = w2_s[j]; d2 += w2; d1 += eta_s[j] - w2; }
    d1 = warp_sum(d1);
    d2 = warp_sum(d2);
    if (l == 0){ op[2*TWOF] = d1; op[2*TWOF+1] = d2; }
  }

  // ---- release partials; last block per bt does the combine ----
  __syncthreads();
  __threadfence();
  if (tid == 0) flags[0] = (atomicAdd(&g_done_bt[bt], 1) == NSPLIT - 1);
  __syncthreads();
  if (!flags[0]) return;
  __threadfence();   // acquire
  if (tid == 0) g_done_bt[bt] = 0;   // reset for next replay

  // ===== mfinal work =====
  float* msV   = redf;
  float* hsV   = redf + 128;
  float* partV = redf + 256;
  float* ddV   = redf + 280;
  float* lgV   = redf + 284;
  float* fin   = redf + 512;

  float n1 = 0.f, n2 = 0.f;
  #pragma unroll
  for (int sp = 0; sp < NSPLIT; sp++){
    const float* p = g_mpart + ((size_t)bt*NSPLIT + sp)*MP_STRIDE;
    n1 += p[tid];
    n2 += p[TWOF + tid];
  }
  if (tid < 32){
    const float* p = g_mpart + ((size_t)bt*NSPLIT + tid)*MP_STRIDE;
    float d1 = warp_sum(p[2*TWOF]);
    float d2 = warp_sum(p[2*TWOF+1]);
    if (tid == 0){ ddV[0] = d1; ddV[1] = d2; }
  }
  __syncthreads();

  float m1 = n1 / (ddV[0] + 1e-6f);
  float m2 = n2 / (ddV[1] + 1e-6f);
  float ma = (n1 + n2) / (ddV[0] + ddV[1] + 1e-6f);
  msV[tid] = ma;
  if (t == NT-1) d_out[MT_OFF + b*TWOF + tid] = ma;

  float wm1 = w_M[tid], wm2 = w_M[TWOF + tid];
  float q0 = warp_sum(m1*m1);
  float q1 = warp_sum(m1*wm1);
  float q2 = warp_sum(m2*m2);
  float q3 = warp_sum(m2*wm2);
  if (lane == 0){
    partV[warp] = q0; partV[4+warp] = q1; partV[8+warp] = q2; partV[12+warp] = q3;
  }
  __syncthreads();
  if (tid == 0){
    float sq1 = partV[0]+partV[1]+partV[2]+partV[3];
    float dt1 = partV[4]+partV[5]+partV[6]+partV[7];
    float sq2 = partV[8]+partV[9]+partV[10]+partV[11];
    float dt2 = partV[12]+partV[13]+partV[14]+partV[15];
    g_a1[bt] = dt1 / fmaxf(sqrtf(sq1), 1e-12f);
    g_a2[bt] = dt2 / fmaxf(sqrtf(sq2), 1e-12f);
  }

  if (t < TM1){
    float acc = sc_b1[tid];
    #pragma unroll 16
    for (int k = 0; k < TWOF; k++)
      acc = fmaf(g_W1T[k*TWOF + tid], msV[k], acc);
    hsV[tid] = fmaxf(acc, 0.f);
    __syncthreads();
    if (warp < 3){
      float p = 0.f;
      #pragma unroll
      for (int q = 0; q < 4; q++)
        p += hsV[lane + 32*q] * __ldg(&sc_W2[warp*TWOF + lane + 32*q]);
      p = warp_sum(p);
      if (lane == 0) lgV[warp] = p + sc_b2[warp];
    }
    __syncthreads();
    if (tid == 0){
      int cp = g_cnt_pos[b*TM1 + t], cn = g_cnt_neg[b*TM1 + t];
      g_cnt_pos[b*TM1 + t] = 0;
      g_cnt_neg[b*TM1 + t] = 0;
      float pr = (float)cp * (1.0f/NI);
      float nr = (float)cn * (1.0f/NI);
      int lbl = (pr >= 0.6f) ? 0 : ((nr >= 0.6f) ? 1 : 2);
      float mx = fmaxf(lgV[0], fmaxf(lgV[1], lgV[2]));
      float lse = logf(expf(lgV[0]-mx) + expf(lgV[1]-mx) + expf(lgV[2]-mx)) + mx;
      g_sync[b*TM1 + t] = lse - lgV[lbl];
    }
  }

  // ---- release; globally last block does the loss ----
  __syncthreads();
  __threadfence();
  if (tid == 0) flags[1] = (atomicAdd(&g_done_all, 1) == NB*NT - 1);
  __syncthreads();
  if (!flags[1]) return;
  __threadfence();   // acquire
  if (tid == 0) g_done_all = 0;

  // ===== final loss =====
  float bm = *b_M;
  float acc = 0.f;
  if (tid < NT*NB){
    int t1 = tid & (NT-1), bb = tid >> 5;
    float a1v = g_a1[bb*NT + t1];
    float sum = 0.f, pos = 0.f;
    #pragma unroll 4
    for (int t2 = 0; t2 < NT; t2++){
      float sc = a1v + g_a2[bb*NT + t2] + bm;
      sc = fminf(fmaxf(sc, -10.f), 10.f);
      float tw = 1.0f / (fabsf((float)(t1 - t2)) + 1.0f);
      float w = expf(sc * tw);
      sum += w;
      if (t2 == t1) pos = w;
    }
    acc = logf(sum + 1e-8f) - logf(pos);
  }
  acc = warp_sum(acc);
  if (lane == 0) fin[warp] = acc;
  float sv = (tid < NB*TM1) ? g_sync[tid] : 0.f;
  sv = warp_sum(sv);
  if (lane == 0) fin[4 + warp] = sv;
  __syncthreads();
  if (tid == 0){
    float lc = (fin[0]+fin[1]+fin[2]+fin[3]) * (1.0f/(NT*NB));
    float ls = (fin[4]+fin[5]+fin[6]+fin[7]) * (1.0f/(NB*TM1));
    d_out[LOSS_OFF] = lc + ls;
  }
}

// ---------------- launch ----------------
extern "C" void kernel_launch(void* const* d_in, const int* in_sizes, int n_in,
                              void* d_out, int out_size){
  const float* e_seq = (const float*)d_in[0];
  const float* Ws_w  = (const float*)d_in[2];
  const float* Ws_b  = (const float*)d_in[3];
  const float* Wiota = (const float*)d_in[4];
  const float* w_eta = (const float*)d_in[5];
  const float* w_M   = (const float*)d_in[6];
  const float* b_M   = (const float*)d_in[7];
  const float* sc_W1 = (const float*)d_in[8];
  const float* sc_b1 = (const float*)d_in[9];
  const float* sc_W2 = (const float*)d_in[10];
  const float* sc_b2 = (const float*)d_in[11];
  const int*  perms  = (const int*)d_in[12];
  const int*  cidx   = (const int*)d_in[13];
  float* out = (float*)d_out;

  k_main<<<dim3(NI/2, NB+1), 256>>>(e_seq, Ws_w, Ws_b, w_eta, cidx,
                                    Wiota, perms, sc_W1, out);
  k_msum<<<dim3(NB*NT, NSPLIT), 128>>>(e_seq, w_M, sc_b1, sc_W2, sc_b2, b_M, out);
}

// round 13
// speedup vs baseline: 1.0324x; 1.0324x over previous
#include <cuda_runtime.h>
#include <cuda_bf16.h>
#include <math.h>
#include <stdint.h>

#define NB 2
#define NT 32
#define NI 2048
#define NF 64
#define TWOF 128
#define NL 5
#define NSPLIT 16
#define CHUNK 128
#define TM1 31
#define MP_STRIDE 264

#define RT_SIZE (NB*NI*TWOF)          // 524288
#define MT_OFF  RT_SIZE
#define LOSS_OFF (RT_SIZE + NB*TWOF)  // 524544

#define ES_STRIDE 68
#define ES_TILE   (32*ES_STRIDE)
#define SS_STRIDE 33

// ---------------- scratch (device globals: allocation-free, zero-init at load) ----
__device__ __nv_bfloat16 g_rall[NB*NT*NI*TWOF];  // r_all (e|rh) in bf16, 33.5MB
__device__ float g_eta[NB*NT*NI];
__device__ float g_W1T[TWOF*TWOF];               // sc_W1 transposed
__device__ unsigned char g_member[NT*NI];
__device__ int   g_cnt_pos[NB*TM1];              // self-zeroing
__device__ int   g_cnt_neg[NB*TM1];
__device__ float g_mpart[NB*NT*NSPLIT*MP_STRIDE];
__device__ float g_a1[NB*NT];
__device__ float g_a2[NB*NT];
__device__ float g_sync[NB*TM1];
__device__ int   g_done_bt[NB*NT];               // self-zeroing
__device__ int   g_done_all;                     // self-zeroing

__device__ __forceinline__ float warp_sum(float v){
  #pragma unroll
  for (int o = 16; o > 0; o >>= 1) v += __shfl_xor_sync(0xffffffffu, v, o);
  return v;
}

__device__ __forceinline__ uint32_t f2tf32(float x){
  uint32_t r;
  asm("cvt.rna.tf32.f32 %0, %1;" : "=r"(r) : "f"(x));
  return r;
}

__device__ __forceinline__ void mma_tf32(float c[4], const uint32_t a[4],
                                         uint32_t b0, uint32_t b1){
  asm("mma.sync.aligned.m16n8k8.row.col.f32.tf32.tf32.f32 "
      "{%0,%1,%2,%3},{%4,%5,%6,%7},{%8,%9},{%0,%1,%2,%3};"
      : "+f"(c[0]), "+f"(c[1]), "+f"(c[2]), "+f"(c[3])
      : "r"(a[0]), "r"(a[1]), "r"(a[2]), "r"(a[3]), "r"(b0), "r"(b1));
}

// ---------------- K_main: main blocks (b<NB) + prep blocks (b==NB) ----------------
__global__ __launch_bounds__(256) void k_main(
    const float* __restrict__ e_seq, const float* __restrict__ Ws_w,
    const float* __restrict__ Ws_b, const float* __restrict__ w_eta,
    const int* __restrict__ close_idx_p, const float* __restrict__ Wiota,
    const int* __restrict__ perms, const float* __restrict__ sc_W1,
    float* __restrict__ d_out)
{
  __shared__ float smemA[64*ES_STRIDE];   // 17408B: Wsm -> Ks  (prep: transpose tile)
  __shared__ float Esf[2*ES_TILE];        // 17408B
  __shared__ float Ss[2*32*SS_STRIDE];    //  8448B
  __shared__ float ciS[2];

  int b = blockIdx.y;
  int tid = threadIdx.x;

  // ===== prep blocks: member scatter + W1T transpose =====
  if (b == NB){
    int bx = blockIdx.x;
    if (bx < NT){
      int t = bx;
      for (int j = tid; j < NI; j += 256){
        int p = perms[t*NI + j];
        g_member[t*NI + p] = (unsigned char)(j >= NI/2);
      }
    } else if (bx < NT + 16){
      int p = bx - NT;
      int r = p >> 2, cc = p & 3;
      float* tileT = smemA;   // [32][33]
      for (int x = tid; x < 1024; x += 256){
        int row = x >> 5, col = x & 31;
        tileT[col*33 + row] = sc_W1[(32*r + row)*TWOF + 32*cc + col];
      }
      __syncthreads();
      for (int x = tid; x < 1024; x += 256){
        int row = x >> 5, col = x & 31;
        g_W1T[(32*cc + row)*TWOF + 32*r + col] = tileT[row*33 + col];
      }
    }
    return;
  }

  // ===== main blocks =====
  int i0 = blockIdx.x * 2;
  int warp = tid >> 5, lane = tid & 31;
  int g  = lane >> 2, tg = lane & 3;

  float* Wsm = smemA;
  float* Ks  = smemA;

  if (warp < 2){
    const float4* wi = (const float4*)(Wiota + (size_t)(i0 + warp)*TWOF);
    const float4* wev = (const float4*)w_eta;
    float4 a = wi[lane], bv = wev[lane];
    float s = a.x*bv.x + a.y*bv.y + a.z*bv.z + a.w*bv.w;
    s = warp_sum(s);
    if (lane == 0) ciS[warp] = s;
  }

  {
    const float4* wg = (const float4*)Ws_w;
    #pragma unroll
    for (int x = tid; x < 1024; x += 256){
      int fo = x >> 4, c = x & 15;
      ((float4*)(Wsm + fo*ES_STRIDE))[c] = wg[x];
    }
  }
  {
    #pragma unroll
    for (int x = tid; x < 1024; x += 256){
      int tile = x >> 9, t = (x >> 4) & 31, c = x & 15;
      const float4* eg = (const float4*)(e_seq + ((size_t)b*NT*NI + (i0+tile))*NF);
      ((float4*)(Esf + (tile*32 + t)*ES_STRIDE))[c] = eg[(size_t)t*(NI*16) + c];
    }
  }
  __syncthreads();

  if (warp < 2 && lane < TM1){
    int cidx = *close_idx_p;
    const float* ef = Esf + warp*ES_TILE;
    float c0 = ef[lane*ES_STRIDE + cidx];
    float c1 = ef[(lane+1)*ES_STRIDE + cidx];
    float r = c1 / (c0 + 1e-8f);
    if (r > 1.0f)      atomicAdd(&g_cnt_pos[b*TM1 + lane], 1);
    else if (r < 1.0f) atomicAdd(&g_cnt_neg[b*TM1 + lane], 1);
  }

  // ---- k = e @ Ws^T + b via tf32 mma, hi/lo split ----
  float c[4][4];
  {
    int tl = warp >> 2, mt = (warp >> 1) & 1, nh = warp & 1;
    const float* Et = Esf + tl*ES_TILE + (mt*16)*ES_STRIDE;

    #pragma unroll
    for (int nt = 0; nt < 4; nt++)
      #pragma unroll
      for (int q = 0; q < 4; q++) c[nt][q] = 0.f;

    #pragma unroll
    for (int ks = 0; ks < 8; ks++){
      int k0 = ks*8;
      float af[4];
      af[0] = Et[g*ES_STRIDE + k0 + tg];
      af[1] = Et[(g+8)*ES_STRIDE + k0 + tg];
      af[2] = Et[g*ES_STRIDE + k0 + tg + 4];
      af[3] = Et[(g+8)*ES_STRIDE + k0 + tg + 4];
      uint32_t ah[4], al[4];
      #pragma unroll
      for (int q = 0; q < 4; q++){
        ah[q] = f2tf32(af[q]);
        al[q] = f2tf32(af[q] - __uint_as_float(ah[q]));
      }
      #pragma unroll
      for (int nt = 0; nt < 4; nt++){
        int n0 = nh*32 + nt*8;
        float b0f = Wsm[(n0+g)*ES_STRIDE + k0 + tg];
        float b1f = Wsm[(n0+g)*ES_STRIDE + k0 + tg + 4];
        uint32_t bh0 = f2tf32(b0f), bh1 = f2tf32(b1f);
        uint32_t bl0 = f2tf32(b0f - __uint_as_float(bh0));
        uint32_t bl1 = f2tf32(b1f - __uint_as_float(bh1));
        mma_tf32(c[nt], ah, bh0, bh1);
        mma_tf32(c[nt], ah, bl0, bl1);
        mma_tf32(c[nt], al, bh0, bh1);
      }
    }
  }
  __syncthreads();

  {
    int tl = warp >> 2, mt = (warp >> 1) & 1, nh = warp & 1;
    #pragma unroll
    for (int nt = 0; nt < 4; nt++){
      int n0 = nh*32 + nt*8;
      int col = n0 + 2*tg;
      float bb0 = __ldg(Ws_b + col), bb1 = __ldg(Ws_b + col + 1);
      int r0 = mt*16 + g;
      float* k0p = Ks + (tl*32 + r0)*ES_STRIDE + col;
      float* k1p = Ks + (tl*32 + r0 + 8)*ES_STRIDE + col;
      k0p[0] = c[nt][0] + bb0; k0p[1] = c[nt][1] + bb1;
      k1p[0] = c[nt][2] + bb0; k1p[1] = c[nt][3] + bb1;
    }
  }
  __syncthreads();

  // ---- scores S = (K K^T)/8 per tile ----
  {
    int stile = warp >> 2;
    int smt   = (warp >> 1) & 1;
    int snh   = warp & 1;
    const float* Km = Ks + (stile*32 + smt*16)*ES_STRIDE;
    const float* Kn = Ks + stile*32*ES_STRIDE;

    float sc[2][4];
    #pragma unroll
    for (int u = 0; u < 2; u++)
      #pragma unroll
      for (int q = 0; q < 4; q++) sc[u][q] = 0.f;

    #pragma unroll
    for (int ks = 0; ks < 8; ks++){
      int k0 = ks*8;
      float af[4];
      af[0] = Km[g*ES_STRIDE + k0 + tg];
      af[1] = Km[(g+8)*ES_STRIDE + k0 + tg];
      af[2] = Km[g*ES_STRIDE + k0 + tg + 4];
      af[3] = Km[(g+8)*ES_STRIDE + k0 + tg + 4];
      uint32_t ah[4], al[4];
      #pragma unroll
      for (int q = 0; q < 4; q++){
        ah[q] = f2tf32(af[q]);
        al[q] = f2tf32(af[q] - __uint_as_float(ah[q]));
      }
      #pragma unroll
      for (int u = 0; u < 2; u++){
        int n0 = (2*snh + u)*8;
        float b0f = Kn[(n0+g)*ES_STRIDE + k0 + tg];
        float b1f = Kn[(n0+g)*ES_STRIDE + k0 + tg + 4];
        uint32_t bh0 = f2tf32(b0f), bh1 = f2tf32(b1f);
        uint32_t bl0 = f2tf32(b0f - __uint_as_float(bh0));
        uint32_t bl1 = f2tf32(b1f - __uint_as_float(bh1));
        mma_tf32(sc[u], ah, bh0, bh1);
        mma_tf32(sc[u], ah, bl0, bl1);
        mma_tf32(sc[u], al, bh0, bh1);
      }
    }
    #pragma unroll
    for (int u = 0; u < 2; u++){
      int col = (2*snh + u)*8 + 2*tg;
      int r0 = smt*16 + g;
      float* s0 = Ss + (stile*32 + r0)*SS_STRIDE + col;
      float* s1 = Ss + (stile*32 + r0 + 8)*SS_STRIDE + col;
      s0[0] = sc[u][0]*0.125f; s0[1] = sc[u][1]*0.125f;
      s1[0] = sc[u][2]*0.125f; s1[1] = sc[u][3]*0.125f;
    }
  }
  __syncthreads();

  float we0 = __ldg(w_eta + lane),      we1 = __ldg(w_eta + 32 + lane);
  float we2 = __ldg(w_eta + 64 + lane), we3 = __ldg(w_eta + 96 + lane);

  #pragma unroll
  for (int tile = 0; tile < 2; tile++){
    int i = i0 + tile;
    float ci = ciS[tile];
    const float* Et = Esf + tile*ES_TILE;

    for (int tt = warp; tt < NT; tt += 8){
      const float* Srow = Ss + (tile*32 + tt)*SS_STRIDE;
      float s[NL];
      #pragma unroll
      for (int l = 0; l < NL; l++){
        int t2 = tt - 4 + l;
        s[l] = (t2 >= 0) ? Srow[t2] : -1e30f;
      }
      float mx = s[0];
      #pragma unroll
      for (int l = 1; l < NL; l++) mx = fmaxf(mx, s[l]);
      float pe[NL], psum = 0.f;
      #pragma unroll
      for (int l = 0; l < NL; l++){ pe[l] = expf(s[l] - mx); psum += pe[l]; }
      float inv = 1.0f / psum;
      float rh0 = 0.f, rh1 = 0.f;
      #pragma unroll
      for (int l = 0; l < NL; l++){
        int t2 = tt - 4 + l; if (t2 < 0) t2 = 0;
        float a = pe[l] * inv;
        rh0 += a * Et[t2*ES_STRIDE + lane];
        rh1 += a * Et[t2*ES_STRIDE + 32 + lane];
      }
      float e0 = Et[tt*ES_STRIDE + lane], e1 = Et[tt*ES_STRIDE + 32 + lane];

      __nv_bfloat16* rb = g_rall + (((size_t)b*NT + tt)*NI + i)*TWOF;
      rb[lane]      = __float2bfloat16(e0);
      rb[32 + lane] = __float2bfloat16(e1);
      rb[64 + lane] = __float2bfloat16(rh0);
      rb[96 + lane] = __float2bfloat16(rh1);

      float d = e0*we0 + e1*we1 + rh0*we2 + rh1*we3;
      d = warp_sum(d);
      float eta = fmaxf(d + ci, 0.f);
      if (lane == 0) g_eta[((size_t)b*NT + tt)*NI + i] = eta;

      if (tt == NT-1){
        float* ro = d_out + ((size_t)b*NI + i)*TWOF;
        ro[lane] = e0; ro[32+lane] = e1; ro[64+lane] = rh0; ro[96+lane] = rh1;
      }
    }
  }
}

// ---------------- K_msum + fused tail (bf16-only reads) ----------------
__global__ __launch_bounds__(128) void k_msum(
    const float* __restrict__ w_M,
    const float* __restrict__ sc_b1,
    const float* __restrict__ sc_W2, const float* __restrict__ sc_b2,
    const float* __restrict__ b_M,
    float* __restrict__ d_out)
{
  int bt = blockIdx.x;
  int b = bt / NT, t = bt % NT;
  int s  = blockIdx.y;
  int tid = threadIdx.x;
  int warp = tid >> 5, lane = tid & 31;
  __shared__ float eta_s[CHUNK];
  __shared__ float w2_s[CHUNK];
  __shared__ float4 red[256];
  __shared__ int flags[2];
  float* redf = (float*)red;

  int i0 = s * CHUNK;
  if (tid < CHUNK){
    float e = g_eta[(size_t)bt*NI + i0 + tid];
    eta_s[tid] = e;
    w2_s[tid]  = g_member[t*NI + i0 + tid] ? e : 0.f;
  }
  __syncthreads();

  // thread: fq = lane covers 4 consecutive f (uint2 = 4 bf16); jb = warp strides j
  int fq = tid & 31;
  int jb = tid >> 5;
  float4 a1 = make_float4(0.f,0.f,0.f,0.f);
  float4 a2 = make_float4(0.f,0.f,0.f,0.f);
  {
    const uint2* base = (const uint2*)(g_rall + ((size_t)bt*NI + i0)*TWOF);
    #pragma unroll
    for (int j = jb; j < CHUNK; j += 4){
      uint2 v = base[(size_t)j*32 + fq];
      __nv_bfloat162 p0 = *(__nv_bfloat162*)&v.x;
      __nv_bfloat162 p1 = *(__nv_bfloat162*)&v.y;
      float4 r;
      r.x = __bfloat162float(p0.x); r.y = __bfloat162float(p0.y);
      r.z = __bfloat162float(p1.x); r.w = __bfloat162float(p1.y);
      float w2 = w2_s[j], w1 = eta_s[j] - w2;
      a1.x += w1*r.x; a1.y += w1*r.y; a1.z += w1*r.z; a1.w += w1*r.w;
      a2.x += w2*r.x; a2.y += w2*r.y; a2.z += w2*r.z; a2.w += w2*r.w;
    }
  }
  red[tid] = a1; red[128 + tid] = a2;
  __syncthreads();

  // op layout: f = q*4 + component (q = 0..31)
  float* op = g_mpart + ((size_t)bt*NSPLIT + s)*MP_STRIDE;
  if (tid < 64){
    int which = tid >> 5;   // 0 -> a1, 1 -> a2
    int q = tid & 31;
    float4 sum = red[which*128 + q];
    #pragma unroll
    for (int g2 = 1; g2 < 4; g2++){
      float4 v = red[which*128 + 32*g2 + q];
      sum.x += v.x; sum.y += v.y; sum.z += v.z; sum.w += v.w;
    }
    ((float4*)(op + which*TWOF))[q] = sum;
  } else if (tid < 96){
    int l = tid - 64;
    float d1 = 0.f, d2 = 0.f;
    #pragma unroll
    for (int j = l; j < CHUNK; j += 32){ float w2 = w2_s[j]; d2 += w2; d1 += eta_s[j] - w2; }
    d1 = warp_sum(d1);
    d2 = warp_sum(d2);
    if (l == 0){ op[2*TWOF] = d1; op[2*TWOF+1] = d2; }
  }

  // ---- release partials; last block per bt does the combine ----
  __syncthreads();
  __threadfence();
  if (tid == 0) flags[0] = (atomicAdd(&g_done_bt[bt], 1) == NSPLIT - 1);
  __syncthreads();
  if (!flags[0]) return;
  __threadfence();   // acquire
  if (tid == 0) g_done_bt[bt] = 0;   // reset for next replay

  // ===== mfinal work =====
  float* msV   = redf;
  float* hsV   = redf + 128;
  float* partV = redf + 256;
  float* ddV   = redf + 280;
  float* lgV   = redf + 284;
  float* fin   = redf + 512;

  float n1 = 0.f, n2 = 0.f;
  #pragma unroll
  for (int sp = 0; sp < NSPLIT; sp++){
    const float* p = g_mpart + ((size_t)bt*NSPLIT + sp)*MP_STRIDE;
    n1 += p[tid];
    n2 += p[TWOF + tid];
  }
  if (tid < 16){
    const float* p = g_mpart + ((size_t)bt*NSPLIT + tid)*MP_STRIDE;
    float d1 = p[2*TWOF], d2 = p[2*TWOF+1];
    #pragma unroll
    for (int o = 8; o > 0; o >>= 1){
      d1 += __shfl_down_sync(0xffffu, d1, o);
      d2 += __shfl_down_sync(0xffffu, d2, o);
    }
    if (tid == 0){ ddV[0] = d1; ddV[1] = d2; }
  }
  __syncthreads();

  float m1 = n1 / (ddV[0] + 1e-6f);
  float m2 = n2 / (ddV[1] + 1e-6f);
  float ma = (n1 + n2) / (ddV[0] + ddV[1] + 1e-6f);
  msV[tid] = ma;
  if (t == NT-1) d_out[MT_OFF + b*TWOF + tid] = ma;

  float wm1 = w_M[tid], wm2 = w_M[TWOF + tid];
  float q0 = warp_sum(m1*m1);
  float q1 = warp_sum(m1*wm1);
  float q2 = warp_sum(m2*m2);
  float q3 = warp_sum(m2*wm2);
  if (lane == 0){
    partV[warp] = q0; partV[4+warp] = q1; partV[8+warp] = q2; partV[12+warp] = q3;
  }
  __syncthreads();
  if (tid == 0){
    float sq1 = partV[0]+partV[1]+partV[2]+partV[3];
    float dt1 = partV[4]+partV[5]+partV[6]+partV[7];
    float sq2 = partV[8]+partV[9]+partV[10]+partV[11];
    float dt2 = partV[12]+partV[13]+partV[14]+partV[15];
    g_a1[bt] = dt1 / fmaxf(sqrtf(sq1), 1e-12f);
    g_a2[bt] = dt2 / fmaxf(sqrtf(sq2), 1e-12f);
  }

  if (t < TM1){
    float acc = sc_b1[tid];
    #pragma unroll 16
    for (int k = 0; k < TWOF; k++)
      acc = fmaf(g_W1T[k*TWOF + tid], msV[k], acc);
    hsV[tid] = fmaxf(acc, 0.f);
    __syncthreads();
    if (warp < 3){
      float p = 0.f;
      #pragma unroll
      for (int q = 0; q < 4; q++)
        p += hsV[lane + 32*q] * __ldg(&sc_W2[warp*TWOF + lane + 32*q]);
      p = warp_sum(p);
      if (lane == 0) lgV[warp] = p + sc_b2[warp];
    }
    __syncthreads();
    if (tid == 0){
      int cp = g_cnt_pos[b*TM1 + t], cn = g_cnt_neg[b*TM1 + t];
      g_cnt_pos[b*TM1 + t] = 0;
      g_cnt_neg[b*TM1 + t] = 0;
      float pr = (float)cp * (1.0f/NI);
      float nr = (float)cn * (1.0f/NI);
      int lbl = (pr >= 0.6f) ? 0 : ((nr >= 0.6f) ? 1 : 2);
      float mx = fmaxf(lgV[0], fmaxf(lgV[1], lgV[2]));
      float lse = logf(expf(lgV[0]-mx) + expf(lgV[1]-mx) + expf(lgV[2]-mx)) + mx;
      g_sync[b*TM1 + t] = lse - lgV[lbl];
    }
  }

  // ---- release; globally last block does the loss ----
  __syncthreads();
  __threadfence();
  if (tid == 0) flags[1] = (atomicAdd(&g_done_all, 1) == NB*NT - 1);
  __syncthreads();
  if (!flags[1]) return;
  __threadfence();   // acquire
  if (tid == 0) g_done_all = 0;

  // ===== final loss =====
  float bm = *b_M;
  float acc = 0.f;
  if (tid < NT*NB){
    int t1 = tid & (NT-1), bb = tid >> 5;
    float a1v = g_a1[bb*NT + t1];
    float sum = 0.f, pos = 0.f;
    #pragma unroll 4
    for (int t2 = 0; t2 < NT; t2++){
      float sc = a1v + g_a2[bb*NT + t2] + bm;
      sc = fminf(fmaxf(sc, -10.f), 10.f);
      float tw = 1.0f / (fabsf((float)(t1 - t2)) + 1.0f);
      float w = expf(sc * tw);
      sum += w;
      if (t2 == t1) pos = w;
    }
    acc = logf(sum + 1e-8f) - logf(pos);
  }
  acc = warp_sum(acc);
  if (lane == 0) fin[warp] = acc;
  float sv = (tid < NB*TM1) ? g_sync[tid] : 0.f;
  sv = warp_sum(sv);
  if (lane == 0) fin[4 + warp] = sv;
  __syncthreads();
  if (tid == 0){
    float lc = (fin[0]+fin[1]+fin[2]+fin[3]) * (1.0f/(NT*NB));
    float ls = (fin[4]+fin[5]+fin[6]+fin[7]) * (1.0f/(NB*TM1));
    d_out[LOSS_OFF] = lc + ls;
  }
}

// ---------------- launch ----------------
extern "C" void kernel_launch(void* const* d_in, const int* in_sizes, int n_in,
                              void* d_out, int out_size){
  const float* e_seq = (const float*)d_in[0];
  const float* Ws_w  = (const float*)d_in[2];
  const float* Ws_b  = (const float*)d_in[3];
  const float* Wiota = (const float*)d_in[4];
  const float* w_eta = (const float*)d_in[5];
  const float* w_M   = (const float*)d_in[6];
  const float* b_M   = (const float*)d_in[7];
  const float* sc_W1 = (const float*)d_in[8];
  const float* sc_b1 = (const float*)d_in[9];
  const float* sc_W2 = (const float*)d_in[10];
  const float* sc_b2 = (const float*)d_in[11];
  const int*  perms  = (const int*)d_in[12];
  const int*  cidx   = (const int*)d_in[13];
  float* out = (float*)d_out;

  k_main<<<dim3(NI/2, NB+1), 256>>>(e_seq, Ws_w, Ws_b, w_eta, cidx,
                                    Wiota, perms, sc_W1, out);
  k_msum<<<dim3(NB*NT, NSPLIT), 128>>>(w_M, sc_b1, sc_W2, sc_b2, b_M, out);
}

// round 14
// speedup vs baseline: 1.0650x; 1.0316x over previous
#include <cuda_runtime.h>
#include <cuda_bf16.h>
#include <math.h>
#include <stdint.h>

#define NB 2
#define NT 32
#define NI 2048
#define NF 64
#define TWOF 128
#define NL 5
#define NSPLIT 16
#define CHUNK 128
#define TM1 31
#define MP_STRIDE 264

#define RT_SIZE (NB*NI*TWOF)          // 524288
#define MT_OFF  RT_SIZE
#define LOSS_OFF (RT_SIZE + NB*TWOF)  // 524544

#define ES_STRIDE 68
#define ES_TILE   (32*ES_STRIDE)
#define SS_STRIDE 33

// ---------------- scratch (device globals: allocation-free, zero-init at load) ----
__device__ __nv_bfloat16 g_rall[NB*NT*NI*TWOF];  // r_all (e|rh) in bf16, 33.5MB
__device__ float g_eta[NB*NT*NI];
__device__ float g_W1T[TWOF*TWOF];               // sc_W1 transposed
__device__ unsigned char g_member[NT*NI];
__device__ int   g_cnt_pos[NB*TM1];              // self-zeroing
__device__ int   g_cnt_neg[NB*TM1];
__device__ float g_mpart[NB*NT*NSPLIT*MP_STRIDE];
__device__ float g_a1[NB*NT];
__device__ float g_a2[NB*NT];
__device__ float g_sync[NB*TM1];
__device__ int   g_done_bt[NB*NT];               // self-zeroing
__device__ int   g_done_all;                     // self-zeroing

__device__ __forceinline__ float warp_sum(float v){
  #pragma unroll
  for (int o = 16; o > 0; o >>= 1) v += __shfl_xor_sync(0xffffffffu, v, o);
  return v;
}

__device__ __forceinline__ uint32_t f2tf32(float x){
  uint32_t r;
  asm("cvt.rna.tf32.f32 %0, %1;" : "=r"(r) : "f"(x));
  return r;
}

__device__ __forceinline__ void mma_tf32(float c[4], const uint32_t a[4],
                                         uint32_t b0, uint32_t b1){
  asm("mma.sync.aligned.m16n8k8.row.col.f32.tf32.tf32.f32 "
      "{%0,%1,%2,%3},{%4,%5,%6,%7},{%8,%9},{%0,%1,%2,%3};"
      : "+f"(c[0]), "+f"(c[1]), "+f"(c[2]), "+f"(c[3])
      : "r"(a[0]), "r"(a[1]), "r"(a[2]), "r"(a[3]), "r"(b0), "r"(b1));
}

// ---------------- K_main: main blocks (b<NB) + prep blocks (b==NB) ----------------
__global__ __launch_bounds__(256) void k_main(
    const float* __restrict__ e_seq, const float* __restrict__ Ws_w,
    const float* __restrict__ Ws_b, const float* __restrict__ w_eta,
    const int* __restrict__ close_idx_p, const float* __restrict__ Wiota,
    const int* __restrict__ perms, const float* __restrict__ sc_W1,
    float* __restrict__ d_out)
{
  __shared__ float smemA[64*ES_STRIDE];   // 17408B: Wsm -> Ks  (prep: transpose tile)
  __shared__ float Esf[2*ES_TILE];        // 17408B
  __shared__ float Ss[2*32*SS_STRIDE];    //  8448B
  __shared__ float ciS[2];

  int b = blockIdx.y;
  int tid = threadIdx.x;

  // ===== prep blocks: member scatter + W1T transpose =====
  if (b == NB){
    int bx = blockIdx.x;
    if (bx < NT){
      int t = bx;
      for (int j = tid; j < NI; j += 256){
        int p = perms[t*NI + j];
        g_member[t*NI + p] = (unsigned char)(j >= NI/2);
      }
    } else if (bx < NT + 16){
      int p = bx - NT;
      int r = p >> 2, cc = p & 3;
      float* tileT = smemA;   // [32][33]
      for (int x = tid; x < 1024; x += 256){
        int row = x >> 5, col = x & 31;
        tileT[col*33 + row] = sc_W1[(32*r + row)*TWOF + 32*cc + col];
      }
      __syncthreads();
      for (int x = tid; x < 1024; x += 256){
        int row = x >> 5, col = x & 31;
        g_W1T[(32*cc + row)*TWOF + 32*r + col] = tileT[row*33 + col];
      }
    }
    return;
  }

  // ===== main blocks =====
  int i0 = blockIdx.x * 2;
  int warp = tid >> 5, lane = tid & 31;
  int g  = lane >> 2, tg = lane & 3;

  float* Wsm = smemA;
  float* Ks  = smemA;

  if (warp < 2){
    const float4* wi = (const float4*)(Wiota + (size_t)(i0 + warp)*TWOF);
    const float4* wev = (const float4*)w_eta;
    float4 a = wi[lane], bv = wev[lane];
    float s = a.x*bv.x + a.y*bv.y + a.z*bv.z + a.w*bv.w;
    s = warp_sum(s);
    if (lane == 0) ciS[warp] = s;
  }

  {
    const float4* wg = (const float4*)Ws_w;
    #pragma unroll
    for (int x = tid; x < 1024; x += 256){
      int fo = x >> 4, c = x & 15;
      ((float4*)(Wsm + fo*ES_STRIDE))[c] = wg[x];
    }
  }
  {
    #pragma unroll
    for (int x = tid; x < 1024; x += 256){
      int tile = x >> 9, t = (x >> 4) & 31, c = x & 15;
      const float4* eg = (const float4*)(e_seq + ((size_t)b*NT*NI + (i0+tile))*NF);
      ((float4*)(Esf + (tile*32 + t)*ES_STRIDE))[c] = eg[(size_t)t*(NI*16) + c];
    }
  }
  __syncthreads();

  if (warp < 2 && lane < TM1){
    int cidx = *close_idx_p;
    const float* ef = Esf + warp*ES_TILE;
    float c0 = ef[lane*ES_STRIDE + cidx];
    float c1 = ef[(lane+1)*ES_STRIDE + cidx];
    float r = c1 / (c0 + 1e-8f);
    if (r > 1.0f)      atomicAdd(&g_cnt_pos[b*TM1 + lane], 1);
    else if (r < 1.0f) atomicAdd(&g_cnt_neg[b*TM1 + lane], 1);
  }

  // ---- k = e @ Ws^T + b via tf32 mma, hi/lo split ----
  float c[4][4];
  {
    int tl = warp >> 2, mt = (warp >> 1) & 1, nh = warp & 1;
    const float* Et = Esf + tl*ES_TILE + (mt*16)*ES_STRIDE;

    #pragma unroll
    for (int nt = 0; nt < 4; nt++)
      #pragma unroll
      for (int q = 0; q < 4; q++) c[nt][q] = 0.f;

    #pragma unroll
    for (int ks = 0; ks < 8; ks++){
      int k0 = ks*8;
      float af[4];
      af[0] = Et[g*ES_STRIDE + k0 + tg];
      af[1] = Et[(g+8)*ES_STRIDE + k0 + tg];
      af[2] = Et[g*ES_STRIDE + k0 + tg + 4];
      af[3] = Et[(g+8)*ES_STRIDE + k0 + tg + 4];
      uint32_t ah[4], al[4];
      #pragma unroll
      for (int q = 0; q < 4; q++){
        ah[q] = f2tf32(af[q]);
        al[q] = f2tf32(af[q] - __uint_as_float(ah[q]));
      }
      #pragma unroll
      for (int nt = 0; nt < 4; nt++){
        int n0 = nh*32 + nt*8;
        float b0f = Wsm[(n0+g)*ES_STRIDE + k0 + tg];
        float b1f = Wsm[(n0+g)*ES_STRIDE + k0 + tg + 4];
        uint32_t bh0 = f2tf32(b0f), bh1 = f2tf32(b1f);
        uint32_t bl0 = f2tf32(b0f - __uint_as_float(bh0));
        uint32_t bl1 = f2tf32(b1f - __uint_as_float(bh1));
        mma_tf32(c[nt], ah, bh0, bh1);
        mma_tf32(c[nt], ah, bl0, bl1);
        mma_tf32(c[nt], al, bh0, bh1);
      }
    }
  }
  __syncthreads();

  {
    int tl = warp >> 2, mt = (warp >> 1) & 1, nh = warp & 1;
    #pragma unroll
    for (int nt = 0; nt < 4; nt++){
      int n0 = nh*32 + nt*8;
      int col = n0 + 2*tg;
      float bb0 = __ldg(Ws_b + col), bb1 = __ldg(Ws_b + col + 1);
      int r0 = mt*16 + g;
      float* k0p = Ks + (tl*32 + r0)*ES_STRIDE + col;
      float* k1p = Ks + (tl*32 + r0 + 8)*ES_STRIDE + col;
      k0p[0] = c[nt][0] + bb0; k0p[1] = c[nt][1] + bb1;
      k1p[0] = c[nt][2] + bb0; k1p[1] = c[nt][3] + bb1;
    }
  }
  __syncthreads();

  // ---- scores S = (K K^T)/8 per tile ----
  {
    int stile = warp >> 2;
    int smt   = (warp >> 1) & 1;
    int snh   = warp & 1;
    const float* Km = Ks + (stile*32 + smt*16)*ES_STRIDE;
    const float* Kn = Ks + stile*32*ES_STRIDE;

    float sc[2][4];
    #pragma unroll
    for (int u = 0; u < 2; u++)
      #pragma unroll
      for (int q = 0; q < 4; q++) sc[u][q] = 0.f;

    #pragma unroll
    for (int ks = 0; ks < 8; ks++){
      int k0 = ks*8;
      float af[4];
      af[0] = Km[g*ES_STRIDE + k0 + tg];
      af[1] = Km[(g+8)*ES_STRIDE + k0 + tg];
      af[2] = Km[g*ES_STRIDE + k0 + tg + 4];
      af[3] = Km[(g+8)*ES_STRIDE + k0 + tg + 4];
      uint32_t ah[4], al[4];
      #pragma unroll
      for (int q = 0; q < 4; q++){
        ah[q] = f2tf32(af[q]);
        al[q] = f2tf32(af[q] - __uint_as_float(ah[q]));
      }
      #pragma unroll
      for (int u = 0; u < 2; u++){
        int n0 = (2*snh + u)*8;
        float b0f = Kn[(n0+g)*ES_STRIDE + k0 + tg];
        float b1f = Kn[(n0+g)*ES_STRIDE + k0 + tg + 4];
        uint32_t bh0 = f2tf32(b0f), bh1 = f2tf32(b1f);
        uint32_t bl0 = f2tf32(b0f - __uint_as_float(bh0));
        uint32_t bl1 = f2tf32(b1f - __uint_as_float(bh1));
        mma_tf32(sc[u], ah, bh0, bh1);
        mma_tf32(sc[u], ah, bl0, bl1);
        mma_tf32(sc[u], al, bh0, bh1);
      }
    }
    #pragma unroll
    for (int u = 0; u < 2; u++){
      int col = (2*snh + u)*8 + 2*tg;
      int r0 = smt*16 + g;
      float* s0 = Ss + (stile*32 + r0)*SS_STRIDE + col;
      float* s1 = Ss + (stile*32 + r0 + 8)*SS_STRIDE + col;
      s0[0] = sc[u][0]*0.125f; s0[1] = sc[u][1]*0.125f;
      s1[0] = sc[u][2]*0.125f; s1[1] = sc[u][3]*0.125f;
    }
  }
  __syncthreads();

  float we0 = __ldg(w_eta + lane),      we1 = __ldg(w_eta + 32 + lane);
  float we2 = __ldg(w_eta + 64 + lane), we3 = __ldg(w_eta + 96 + lane);

  #pragma unroll
  for (int tile = 0; tile < 2; tile++){
    int i = i0 + tile;
    float ci = ciS[tile];
    const float* Et = Esf + tile*ES_TILE;

    for (int tt = warp; tt < NT; tt += 8){
      const float* Srow = Ss + (tile*32 + tt)*SS_STRIDE;
      float s[NL];
      #pragma unroll
      for (int l = 0; l < NL; l++){
        int t2 = tt - 4 + l;
        s[l] = (t2 >= 0) ? Srow[t2] : -1e30f;
      }
      float mx = s[0];
      #pragma unroll
      for (int l = 1; l < NL; l++) mx = fmaxf(mx, s[l]);
      float pe[NL], psum = 0.f;
      #pragma unroll
      for (int l = 0; l < NL; l++){ pe[l] = expf(s[l] - mx); psum += pe[l]; }
      float inv = 1.0f / psum;
      float rh0 = 0.f, rh1 = 0.f;
      #pragma unroll
      for (int l = 0; l < NL; l++){
        int t2 = tt - 4 + l; if (t2 < 0) t2 = 0;
        float a = pe[l] * inv;
        rh0 += a * Et[t2*ES_STRIDE + lane];
        rh1 += a * Et[t2*ES_STRIDE + 32 + lane];
      }
      float e0 = Et[tt*ES_STRIDE + lane], e1 = Et[tt*ES_STRIDE + 32 + lane];

      __nv_bfloat16* rb = g_rall + (((size_t)b*NT + tt)*NI + i)*TWOF;
      rb[lane]      = __float2bfloat16(e0);
      rb[32 + lane] = __float2bfloat16(e1);
      rb[64 + lane] = __float2bfloat16(rh0);
      rb[96 + lane] = __float2bfloat16(rh1);

      float d = e0*we0 + e1*we1 + rh0*we2 + rh1*we3;
      d = warp_sum(d);
      float eta = fmaxf(d + ci, 0.f);
      if (lane == 0) g_eta[((size_t)b*NT + tt)*NI + i] = eta;

      if (tt == NT-1){
        float* ro = d_out + ((size_t)b*NI + i)*TWOF;
        ro[lane] = e0; ro[32+lane] = e1; ro[64+lane] = rh0; ro[96+lane] = rh1;
      }
    }
  }
}

// ---------------- K_msum + fused tail (256 threads, bf16-only reads) ----------------
__global__ __launch_bounds__(256) void k_msum(
    const float* __restrict__ w_M,
    const float* __restrict__ sc_b1,
    const float* __restrict__ sc_W2, const float* __restrict__ sc_b2,
    const float* __restrict__ b_M,
    float* __restrict__ d_out)
{
  int bt = blockIdx.x;
  int b = bt / NT, t = bt % NT;
  int s  = blockIdx.y;
  int tid = threadIdx.x;
  int warp = tid >> 5, lane = tid & 31;
  __shared__ float eta_s[CHUNK];
  __shared__ float w2_s[CHUNK];
  __shared__ float4 red[512];           // 8KB
  __shared__ int flags[2];
  float* redf = (float*)red;

  int i0 = s * CHUNK;
  if (tid < CHUNK){
    float e = g_eta[(size_t)bt*NI + i0 + tid];
    eta_s[tid] = e;
    w2_s[tid]  = g_member[t*NI + i0 + tid] ? e : 0.f;
  }
  __syncthreads();

  // thread: fq = tid&31 covers uint2 (4 bf16); jb = tid>>5 in 0..7, stride 8 -> 16 iters
  int fq = tid & 31;
  int jb = tid >> 5;
  float4 a1 = make_float4(0.f,0.f,0.f,0.f);
  float4 a2 = make_float4(0.f,0.f,0.f,0.f);
  {
    const uint2* base = (const uint2*)(g_rall + ((size_t)bt*NI + i0)*TWOF);
    #pragma unroll
    for (int j = jb; j < CHUNK; j += 8){
      uint2 v = base[(size_t)j*32 + fq];
      __nv_bfloat162 p0 = *(__nv_bfloat162*)&v.x;
      __nv_bfloat162 p1 = *(__nv_bfloat162*)&v.y;
      float4 r;
      r.x = __bfloat162float(p0.x); r.y = __bfloat162float(p0.y);
      r.z = __bfloat162float(p1.x); r.w = __bfloat162float(p1.y);
      float w2 = w2_s[j], w1 = eta_s[j] - w2;
      a1.x += w1*r.x; a1.y += w1*r.y; a1.z += w1*r.z; a1.w += w1*r.w;
      a2.x += w2*r.x; a2.y += w2*r.y; a2.z += w2*r.z; a2.w += w2*r.w;
    }
  }
  red[tid] = a1; red[256 + tid] = a2;
  __syncthreads();

  // op layout: f = q*4 + component (q = 0..31)
  float* op = g_mpart + ((size_t)bt*NSPLIT + s)*MP_STRIDE;
  if (tid < 64){
    int which = tid >> 5;   // 0 -> a1, 1 -> a2
    int q = tid & 31;
    float4 sum = red[which*256 + q];
    #pragma unroll
    for (int g2 = 1; g2 < 8; g2++){
      float4 v = red[which*256 + 32*g2 + q];
      sum.x += v.x; sum.y += v.y; sum.z += v.z; sum.w += v.w;
    }
    ((float4*)(op + which*TWOF))[q] = sum;
  } else if (tid < 96){
    int l = tid - 64;
    float d1 = 0.f, d2 = 0.f;
    #pragma unroll
    for (int j = l; j < CHUNK; j += 32){ float w2 = w2_s[j]; d2 += w2; d1 += eta_s[j] - w2; }
    d1 = warp_sum(d1);
    d2 = warp_sum(d2);
    if (l == 0){ op[2*TWOF] = d1; op[2*TWOF+1] = d2; }
  }

  // ---- release partials; last block per bt does the combine ----
  __syncthreads();
  __threadfence();
  if (tid == 0) flags[0] = (atomicAdd(&g_done_bt[bt], 1) == NSPLIT - 1);
  __syncthreads();
  if (!flags[0]) return;
  __threadfence();   // acquire
  if (tid == 0) g_done_bt[bt] = 0;   // reset for next replay

  // ===== mfinal work =====
  float* msV   = redf;          // [128]
  float* hsV   = redf + 128;    // [128]
  float* partV = redf + 256;    // [16]
  float* ddV   = redf + 280;    // [2]
  float* lgV   = redf + 284;    // [3]
  float* finA  = redf + 512;    // [8]
  float* finB  = redf + 520;    // [8]

  float n1 = 0.f, n2 = 0.f;
  if (tid < TWOF){
    #pragma unroll
    for (int sp = 0; sp < NSPLIT; sp++){
      const float* p = g_mpart + ((size_t)bt*NSPLIT + sp)*MP_STRIDE;
      n1 += p[tid];
      n2 += p[TWOF + tid];
    }
  }
  if (tid < 16){
    const float* p = g_mpart + ((size_t)bt*NSPLIT + tid)*MP_STRIDE;
    float d1 = p[2*TWOF], d2 = p[2*TWOF+1];
    #pragma unroll
    for (int o = 8; o > 0; o >>= 1){
      d1 += __shfl_down_sync(0xffffu, d1, o);
      d2 += __shfl_down_sync(0xffffu, d2, o);
    }
    if (tid == 0){ ddV[0] = d1; ddV[1] = d2; }
  }
  __syncthreads();

  if (tid < TWOF){
    float m1 = n1 / (ddV[0] + 1e-6f);
    float m2 = n2 / (ddV[1] + 1e-6f);
    float ma = (n1 + n2) / (ddV[0] + ddV[1] + 1e-6f);
    msV[tid] = ma;
    if (t == NT-1) d_out[MT_OFF + b*TWOF + tid] = ma;

    float wm1 = w_M[tid], wm2 = w_M[TWOF + tid];
    float q0 = warp_sum(m1*m1);
    float q1 = warp_sum(m1*wm1);
    float q2 = warp_sum(m2*m2);
    float q3 = warp_sum(m2*wm2);
    if (lane == 0){
      partV[warp] = q0; partV[4+warp] = q1; partV[8+warp] = q2; partV[12+warp] = q3;
    }
  }
  __syncthreads();
  if (tid == 0){
    float sq1 = partV[0]+partV[1]+partV[2]+partV[3];
    float dt1 = partV[4]+partV[5]+partV[6]+partV[7];
    float sq2 = partV[8]+partV[9]+partV[10]+partV[11];
    float dt2 = partV[12]+partV[13]+partV[14]+partV[15];
    g_a1[bt] = dt1 / fmaxf(sqrtf(sq1), 1e-12f);
    g_a2[bt] = dt2 / fmaxf(sqrtf(sq2), 1e-12f);
  }

  if (t < TM1){
    if (tid < TWOF){
      float acc = sc_b1[tid];
      #pragma unroll 16
      for (int k = 0; k < TWOF; k++)
        acc = fmaf(g_W1T[k*TWOF + tid], msV[k], acc);
      hsV[tid] = fmaxf(acc, 0.f);
    }
    __syncthreads();
    if (warp < 3){
      float p = 0.f;
      #pragma unroll
      for (int q = 0; q < 4; q++)
        p += hsV[lane + 32*q] * __ldg(&sc_W2[warp*TWOF + lane + 32*q]);
      p = warp_sum(p);
      if (lane == 0) lgV[warp] = p + sc_b2[warp];
    }
    __syncthreads();
    if (tid == 0){
      int cp = g_cnt_pos[b*TM1 + t], cn = g_cnt_neg[b*TM1 + t];
      g_cnt_pos[b*TM1 + t] = 0;
      g_cnt_neg[b*TM1 + t] = 0;
      float pr = (float)cp * (1.0f/NI);
      float nr = (float)cn * (1.0f/NI);
      int lbl = (pr >= 0.6f) ? 0 : ((nr >= 0.6f) ? 1 : 2);
      float mx = fmaxf(lgV[0], fmaxf(lgV[1], lgV[2]));
      float lse = logf(expf(lgV[0]-mx) + expf(lgV[1]-mx) + expf(lgV[2]-mx)) + mx;
      g_sync[b*TM1 + t] = lse - lgV[lbl];
    }
  }

  // ---- release; globally last block does the loss ----
  __syncthreads();
  __threadfence();
  if (tid == 0) flags[1] = (atomicAdd(&g_done_all, 1) == NB*NT - 1);
  __syncthreads();
  if (!flags[1]) return;
  __threadfence();   // acquire
  if (tid == 0) g_done_all = 0;

  // ===== final loss =====
  float bm = *b_M;
  float acc = 0.f;
  if (tid < NT*NB){
    int t1 = tid & (NT-1), bb = tid >> 5;
    float a1v = g_a1[bb*NT + t1];
    float sum = 0.f, pos = 0.f;
    #pragma unroll 4
    for (int t2 = 0; t2 < NT; t2++){
      float sc = a1v + g_a2[bb*NT + t2] + bm;
      sc = fminf(fmaxf(sc, -10.f), 10.f);
      float tw = 1.0f / (fabsf((float)(t1 - t2)) + 1.0f);
      float w = expf(sc * tw);
      sum += w;
      if (t2 == t1) pos = w;
    }
    acc = logf(sum + 1e-8f) - logf(pos);
  }
  acc = warp_sum(acc);
  if (lane == 0) finA[warp] = acc;
  float sv = (tid < NB*TM1) ? g_sync[tid] : 0.f;
  sv = warp_sum(sv);
  if (lane == 0) finB[warp] = sv;
  __syncthreads();
  if (tid == 0){
    float lc = 0.f, ls = 0.f;
    #pragma unroll
    for (int w = 0; w < 8; w++){ lc += finA[w]; ls += finB[w]; }
    d_out[LOSS_OFF] = lc * (1.0f/(NT*NB)) + ls * (1.0f/(NB*TM1));
  }
}

// ---------------- launch ----------------
extern "C" void kernel_launch(void* const* d_in, const int* in_sizes, int n_in,
                              void* d_out, int out_size){
  const float* e_seq = (const float*)d_in[0];
  const float* Ws_w  = (const float*)d_in[2];
  const float* Ws_b  = (const float*)d_in[3];
  const float* Wiota = (const float*)d_in[4];
  const float* w_eta = (const float*)d_in[5];
  const float* w_M   = (const float*)d_in[6];
  const float* b_M   = (const float*)d_in[7];
  const float* sc_W1 = (const float*)d_in[8];
  const float* sc_b1 = (const float*)d_in[9];
  const float* sc_W2 = (const float*)d_in[10];
  const float* sc_b2 = (const float*)d_in[11];
  const int*  perms  = (const int*)d_in[12];
  const int*  cidx   = (const int*)d_in[13];
  float* out = (float*)d_out;

  k_main<<<dim3(NI/2, NB+1), 256>>>(e_seq, Ws_w, Ws_b, w_eta, cidx,
                                    Wiota, perms, sc_W1, out);
  k_msum<<<dim3(NB*NT, NSPLIT), 256>>>(w_M, sc_b1, sc_W2, sc_b2, b_M, out);
}

// round 15
// speedup vs baseline: 1.0867x; 1.0204x over previous
#include <cuda_runtime.h>
#include <cuda_bf16.h>
#include <math.h>
#include <stdint.h>

#define NB 2
#define NT 32
#define NI 2048
#define NF 64
#define TWOF 128
#define NL 5
#define NSPLIT 16
#define CHUNK 128
#define TM1 31
#define MP_STRIDE 264

#define RT_SIZE (NB*NI*TWOF)          // 524288
#define MT_OFF  RT_SIZE
#define LOSS_OFF (RT_SIZE + NB*TWOF)  // 524544

#define ES_STRIDE 68
#define ES_TILE   (32*ES_STRIDE)
#define SS_STRIDE 33

// ---------------- scratch (device globals: allocation-free, zero-init at load) ----
__device__ __nv_bfloat16 g_rall[NB*NT*NI*TWOF];  // r_all (e|rh) in bf16, 33.5MB
__device__ float g_eta[NB*NT*NI];
__device__ float g_W1T[TWOF*TWOF];               // sc_W1 transposed
__device__ unsigned char g_member[NT*NI];
__device__ int   g_cnt_pos[NB*TM1];              // self-zeroing
__device__ int   g_cnt_neg[NB*TM1];
__device__ float g_mpart[NB*NT*NSPLIT*MP_STRIDE];
__device__ float g_a1[NB*NT];
__device__ float g_a2[NB*NT];
__device__ float g_sync[NB*TM1];
__device__ int   g_done_bt[NB*NT];               // self-zeroing
__device__ int   g_done_all;                     // self-zeroing

__device__ __forceinline__ float warp_sum(float v){
  #pragma unroll
  for (int o = 16; o > 0; o >>= 1) v += __shfl_xor_sync(0xffffffffu, v, o);
  return v;
}

__device__ __forceinline__ uint32_t f2tf32(float x){
  uint32_t r;
  asm("cvt.rna.tf32.f32 %0, %1;" : "=r"(r) : "f"(x));
  return r;
}

__device__ __forceinline__ void mma_tf32(float c[4], const uint32_t a[4],
                                         uint32_t b0, uint32_t b1){
  asm("mma.sync.aligned.m16n8k8.row.col.f32.tf32.tf32.f32 "
      "{%0,%1,%2,%3},{%4,%5,%6,%7},{%8,%9},{%0,%1,%2,%3};"
      : "+f"(c[0]), "+f"(c[1]), "+f"(c[2]), "+f"(c[3])
      : "r"(a[0]), "r"(a[1]), "r"(a[2]), "r"(a[3]), "r"(b0), "r"(b1));
}

// ---------------- K_main: main blocks (b<NB) + prep blocks (b==NB) ----------------
__global__ __launch_bounds__(256) void k_main(
    const float* __restrict__ e_seq, const float* __restrict__ Ws_w,
    const float* __restrict__ Ws_b, const float* __restrict__ w_eta,
    const int* __restrict__ close_idx_p, const float* __restrict__ Wiota,
    const int* __restrict__ perms, const float* __restrict__ sc_W1,
    float* __restrict__ d_out)
{
  __shared__ float smemA[64*ES_STRIDE];   // 17408B: Wsm -> Ks  (prep: transpose tile)
  __shared__ float Esf[2*ES_TILE];        // 17408B
  __shared__ float Ss[2*32*SS_STRIDE];    //  8448B
  __shared__ float ciS[2];

  int b = blockIdx.y;
  int tid = threadIdx.x;

  // ===== prep blocks: member scatter + W1T transpose =====
  if (b == NB){
    int bx = blockIdx.x;
    if (bx < NT){
      int t = bx;
      for (int j = tid; j < NI; j += 256){
        int p = perms[t*NI + j];
        g_member[t*NI + p] = (unsigned char)(j >= NI/2);
      }
    } else if (bx < NT + 16){
      int p = bx - NT;
      int r = p >> 2, cc = p & 3;
      float* tileT = smemA;   // [32][33]
      for (int x = tid; x < 1024; x += 256){
        int row = x >> 5, col = x & 31;
        tileT[col*33 + row] = sc_W1[(32*r + row)*TWOF + 32*cc + col];
      }
      __syncthreads();
      for (int x = tid; x < 1024; x += 256){
        int row = x >> 5, col = x & 31;
        g_W1T[(32*cc + row)*TWOF + 32*r + col] = tileT[row*33 + col];
      }
    }
    return;
  }

  // ===== main blocks =====
  int i0 = blockIdx.x * 2;
  int warp = tid >> 5, lane = tid & 31;
  int g  = lane >> 2, tg = lane & 3;

  float* Wsm = smemA;
  float* Ks  = smemA;

  if (warp < 2){
    const float4* wi = (const float4*)(Wiota + (size_t)(i0 + warp)*TWOF);
    const float4* wev = (const float4*)w_eta;
    float4 a = wi[lane], bv = wev[lane];
    float s = a.x*bv.x + a.y*bv.y + a.z*bv.z + a.w*bv.w;
    s = warp_sum(s);
    if (lane == 0) ciS[warp] = s;
  }

  {
    const float4* wg = (const float4*)Ws_w;
    #pragma unroll
    for (int x = tid; x < 1024; x += 256){
      int fo = x >> 4, c = x & 15;
      ((float4*)(Wsm + fo*ES_STRIDE))[c] = wg[x];
    }
  }
  {
    #pragma unroll
    for (int x = tid; x < 1024; x += 256){
      int tile = x >> 9, t = (x >> 4) & 31, c = x & 15;
      const float4* eg = (const float4*)(e_seq + ((size_t)b*NT*NI + (i0+tile))*NF);
      ((float4*)(Esf + (tile*32 + t)*ES_STRIDE))[c] = eg[(size_t)t*(NI*16) + c];
    }
  }
  __syncthreads();

  if (warp < 2 && lane < TM1){
    int cidx = *close_idx_p;
    const float* ef = Esf + warp*ES_TILE;
    float c0 = ef[lane*ES_STRIDE + cidx];
    float c1 = ef[(lane+1)*ES_STRIDE + cidx];
    float r = c1 / (c0 + 1e-8f);
    if (r > 1.0f)      atomicAdd(&g_cnt_pos[b*TM1 + lane], 1);
    else if (r < 1.0f) atomicAdd(&g_cnt_neg[b*TM1 + lane], 1);
  }

  // ---- k = e @ Ws^T + b via tf32 mma, hi/lo split ----
  float c[4][4];
  {
    int tl = warp >> 2, mt = (warp >> 1) & 1, nh = warp & 1;
    const float* Et = Esf + tl*ES_TILE + (mt*16)*ES_STRIDE;

    #pragma unroll
    for (int nt = 0; nt < 4; nt++)
      #pragma unroll
      for (int q = 0; q < 4; q++) c[nt][q] = 0.f;

    #pragma unroll
    for (int ks = 0; ks < 8; ks++){
      int k0 = ks*8;
      float af[4];
      af[0] = Et[g*ES_STRIDE + k0 + tg];
      af[1] = Et[(g+8)*ES_STRIDE + k0 + tg];
      af[2] = Et[g*ES_STRIDE + k0 + tg + 4];
      af[3] = Et[(g+8)*ES_STRIDE + k0 + tg + 4];
      uint32_t ah[4], al[4];
      #pragma unroll
      for (int q = 0; q < 4; q++){
        ah[q] = f2tf32(af[q]);
        al[q] = f2tf32(af[q] - __uint_as_float(ah[q]));
      }
      #pragma unroll
      for (int nt = 0; nt < 4; nt++){
        int n0 = nh*32 + nt*8;
        float b0f = Wsm[(n0+g)*ES_STRIDE + k0 + tg];
        float b1f = Wsm[(n0+g)*ES_STRIDE + k0 + tg + 4];
        uint32_t bh0 = f2tf32(b0f), bh1 = f2tf32(b1f);
        uint32_t bl0 = f2tf32(b0f - __uint_as_float(bh0));
        uint32_t bl1 = f2tf32(b1f - __uint_as_float(bh1));
        mma_tf32(c[nt], ah, bh0, bh1);
        mma_tf32(c[nt], ah, bl0, bl1);
        mma_tf32(c[nt], al, bh0, bh1);
      }
    }
  }
  __syncthreads();

  {
    int tl = warp >> 2, mt = (warp >> 1) & 1, nh = warp & 1;
    #pragma unroll
    for (int nt = 0; nt < 4; nt++){
      int n0 = nh*32 + nt*8;
      int col = n0 + 2*tg;
      float bb0 = __ldg(Ws_b + col), bb1 = __ldg(Ws_b + col + 1);
      int r0 = mt*16 + g;
      float* k0p = Ks + (tl*32 + r0)*ES_STRIDE + col;
      float* k1p = Ks + (tl*32 + r0 + 8)*ES_STRIDE + col;
      k0p[0] = c[nt][0] + bb0; k0p[1] = c[nt][1] + bb1;
      k1p[0] = c[nt][2] + bb0; k1p[1] = c[nt][3] + bb1;
    }
  }
  __syncthreads();

  // ---- scores S = (K K^T)/8 per tile ----
  {
    int stile = warp >> 2;
    int smt   = (warp >> 1) & 1;
    int snh   = warp & 1;
    const float* Km = Ks + (stile*32 + smt*16)*ES_STRIDE;
    const float* Kn = Ks + stile*32*ES_STRIDE;

    float sc[2][4];
    #pragma unroll
    for (int u = 0; u < 2; u++)
      #pragma unroll
      for (int q = 0; q < 4; q++) sc[u][q] = 0.f;

    #pragma unroll
    for (int ks = 0; ks < 8; ks++){
      int k0 = ks*8;
      float af[4];
      af[0] = Km[g*ES_STRIDE + k0 + tg];
      af[1] = Km[(g+8)*ES_STRIDE + k0 + tg];
      af[2] = Km[g*ES_STRIDE + k0 + tg + 4];
      af[3] = Km[(g+8)*ES_STRIDE + k0 + tg + 4];
      uint32_t ah[4], al[4];
      #pragma unroll
      for (int q = 0; q < 4; q++){
        ah[q] = f2tf32(af[q]);
        al[q] = f2tf32(af[q] - __uint_as_float(ah[q]));
      }
      #pragma unroll
      for (int u = 0; u < 2; u++){
        int n0 = (2*snh + u)*8;
        float b0f = Kn[(n0+g)*ES_STRIDE + k0 + tg];
        float b1f = Kn[(n0+g)*ES_STRIDE + k0 + tg + 4];
        uint32_t bh0 = f2tf32(b0f), bh1 = f2tf32(b1f);
        uint32_t bl0 = f2tf32(b0f - __uint_as_float(bh0));
        uint32_t bl1 = f2tf32(b1f - __uint_as_float(bh1));
        mma_tf32(sc[u], ah, bh0, bh1);
        mma_tf32(sc[u], ah, bl0, bl1);
        mma_tf32(sc[u], al, bh0, bh1);
      }
    }
    #pragma unroll
    for (int u = 0; u < 2; u++){
      int col = (2*snh + u)*8 + 2*tg;
      int r0 = smt*16 + g;
      float* s0 = Ss + (stile*32 + r0)*SS_STRIDE + col;
      float* s1 = Ss + (stile*32 + r0 + 8)*SS_STRIDE + col;
      s0[0] = sc[u][0]*0.125f; s0[1] = sc[u][1]*0.125f;
      s1[0] = sc[u][2]*0.125f; s1[1] = sc[u][3]*0.125f;
    }
  }
  __syncthreads();

  float we0 = __ldg(w_eta + lane),      we1 = __ldg(w_eta + 32 + lane);
  float we2 = __ldg(w_eta + 64 + lane), we3 = __ldg(w_eta + 96 + lane);

  #pragma unroll
  for (int tile = 0; tile < 2; tile++){
    int i = i0 + tile;
    float ci = ciS[tile];
    const float* Et = Esf + tile*ES_TILE;

    for (int tt = warp; tt < NT; tt += 8){
      const float* Srow = Ss + (tile*32 + tt)*SS_STRIDE;
      float s[NL];
      #pragma unroll
      for (int l = 0; l < NL; l++){
        int t2 = tt - 4 + l;
        s[l] = (t2 >= 0) ? Srow[t2] : -1e30f;
      }
      float mx = s[0];
      #pragma unroll
      for (int l = 1; l < NL; l++) mx = fmaxf(mx, s[l]);
      float pe[NL], psum = 0.f;
      #pragma unroll
      for (int l = 0; l < NL; l++){ pe[l] = __expf(s[l] - mx); psum += pe[l]; }
      float inv = 1.0f / psum;
      float rh0 = 0.f, rh1 = 0.f;
      #pragma unroll
      for (int l = 0; l < NL; l++){
        int t2 = tt - 4 + l; if (t2 < 0) t2 = 0;
        float a = pe[l] * inv;
        rh0 += a * Et[t2*ES_STRIDE + lane];
        rh1 += a * Et[t2*ES_STRIDE + 32 + lane];
      }
      float e0 = Et[tt*ES_STRIDE + lane], e1 = Et[tt*ES_STRIDE + 32 + lane];

      __nv_bfloat16* rb = g_rall + (((size_t)b*NT + tt)*NI + i)*TWOF;
      rb[lane]      = __float2bfloat16(e0);
      rb[32 + lane] = __float2bfloat16(e1);
      rb[64 + lane] = __float2bfloat16(rh0);
      rb[96 + lane] = __float2bfloat16(rh1);

      float d = e0*we0 + e1*we1 + rh0*we2 + rh1*we3;
      d = warp_sum(d);
      float eta = fmaxf(d + ci, 0.f);
      if (lane == 0) g_eta[((size_t)b*NT + tt)*NI + i] = eta;

      if (tt == NT-1){
        float* ro = d_out + ((size_t)b*NI + i)*TWOF;
        ro[lane] = e0; ro[32+lane] = e1; ro[64+lane] = rh0; ro[96+lane] = rh1;
      }
    }
  }
}

// ---------------- K_msum + fused tail (256 threads, bf16-only reads) ----------------
__global__ __launch_bounds__(256) void k_msum(
    const float* __restrict__ w_M,
    const float* __restrict__ sc_b1,
    const float* __restrict__ sc_W2, const float* __restrict__ sc_b2,
    const float* __restrict__ b_M,
    float* __restrict__ d_out)
{
  int bt = blockIdx.x;
  int b = bt / NT, t = bt % NT;
  int s  = blockIdx.y;
  int tid = threadIdx.x;
  int warp = tid >> 5, lane = tid & 31;
  __shared__ float eta_s[CHUNK];
  __shared__ float w2_s[CHUNK];
  __shared__ float4 red[512];           // 8KB
  __shared__ int flags[2];
  float* redf = (float*)red;

  int i0 = s * CHUNK;
  if (tid < CHUNK){
    float e = g_eta[(size_t)bt*NI + i0 + tid];
    eta_s[tid] = e;
    w2_s[tid]  = g_member[t*NI + i0 + tid] ? e : 0.f;
  }
  __syncthreads();

  int fq = tid & 31;
  int jb = tid >> 5;
  float4 a1 = make_float4(0.f,0.f,0.f,0.f);
  float4 a2 = make_float4(0.f,0.f,0.f,0.f);
  {
    const uint2* base = (const uint2*)(g_rall + ((size_t)bt*NI + i0)*TWOF);
    #pragma unroll
    for (int j = jb; j < CHUNK; j += 8){
      uint2 v = base[(size_t)j*32 + fq];
      __nv_bfloat162 p0 = *(__nv_bfloat162*)&v.x;
      __nv_bfloat162 p1 = *(__nv_bfloat162*)&v.y;
      float4 r;
      r.x = __bfloat162float(p0.x); r.y = __bfloat162float(p0.y);
      r.z = __bfloat162float(p1.x); r.w = __bfloat162float(p1.y);
      float w2 = w2_s[j], w1 = eta_s[j] - w2;
      a1.x += w1*r.x; a1.y += w1*r.y; a1.z += w1*r.z; a1.w += w1*r.w;
      a2.x += w2*r.x; a2.y += w2*r.y; a2.z += w2*r.z; a2.w += w2*r.w;
    }
  }
  red[tid] = a1; red[256 + tid] = a2;
  __syncthreads();

  float* op = g_mpart + ((size_t)bt*NSPLIT + s)*MP_STRIDE;
  if (tid < 64){
    int which = tid >> 5;
    int q = tid & 31;
    float4 sum = red[which*256 + q];
    #pragma unroll
    for (int g2 = 1; g2 < 8; g2++){
      float4 v = red[which*256 + 32*g2 + q];
      sum.x += v.x; sum.y += v.y; sum.z += v.z; sum.w += v.w;
    }
    ((float4*)(op + which*TWOF))[q] = sum;
  } else if (tid < 96){
    int l = tid - 64;
    float d1 = 0.f, d2 = 0.f;
    #pragma unroll
    for (int j = l; j < CHUNK; j += 32){ float w2 = w2_s[j]; d2 += w2; d1 += eta_s[j] - w2; }
    d1 = warp_sum(d1);
    d2 = warp_sum(d2);
    if (l == 0){ op[2*TWOF] = d1; op[2*TWOF+1] = d2; }
  }

  // ---- release partials; last block per bt does the combine ----
  __syncthreads();
  __threadfence();
  if (tid == 0) flags[0] = (atomicAdd(&g_done_bt[bt], 1) == NSPLIT - 1);
  __syncthreads();
  if (!flags[0]) return;
  __threadfence();   // acquire
  if (tid == 0) g_done_bt[bt] = 0;   // reset for next replay

  // ===== mfinal work =====
  float* msV   = redf;          // [128]
  float* hsV   = redf + 128;    // [128]
  float* partV = redf + 256;    // [16]
  float* ddV   = redf + 280;    // [2]
  float* lgV   = redf + 284;    // [3]
  float* finA  = redf + 512;    // [8]
  float* finB  = redf + 520;    // [8]

  float n1 = 0.f, n2 = 0.f;
  if (tid < TWOF){
    #pragma unroll
    for (int sp = 0; sp < NSPLIT; sp++){
      const float* p = g_mpart + ((size_t)bt*NSPLIT + sp)*MP_STRIDE;
      n1 += p[tid];
      n2 += p[TWOF + tid];
    }
  }
  if (tid < 16){
    const float* p = g_mpart + ((size_t)bt*NSPLIT + tid)*MP_STRIDE;
    float d1 = p[2*TWOF], d2 = p[2*TWOF+1];
    #pragma unroll
    for (int o = 8; o > 0; o >>= 1){
      d1 += __shfl_down_sync(0xffffu, d1, o);
      d2 += __shfl_down_sync(0xffffu, d2, o);
    }
    if (tid == 0){ ddV[0] = d1; ddV[1] = d2; }
  }
  __syncthreads();

  if (tid < TWOF){
    float m1 = n1 / (ddV[0] + 1e-6f);
    float m2 = n2 / (ddV[1] + 1e-6f);
    float ma = (n1 + n2) / (ddV[0] + ddV[1] + 1e-6f);
    msV[tid] = ma;
    if (t == NT-1) d_out[MT_OFF + b*TWOF + tid] = ma;

    float wm1 = w_M[tid], wm2 = w_M[TWOF + tid];
    float q0 = warp_sum(m1*m1);
    float q1 = warp_sum(m1*wm1);
    float q2 = warp_sum(m2*m2);
    float q3 = warp_sum(m2*wm2);
    if (lane == 0){
      partV[warp] = q0; partV[4+warp] = q1; partV[8+warp] = q2; partV[12+warp] = q3;
    }
  }
  __syncthreads();
  if (tid == 0){
    float sq1 = partV[0]+partV[1]+partV[2]+partV[3];
    float dt1 = partV[4]+partV[5]+partV[6]+partV[7];
    float sq2 = partV[8]+partV[9]+partV[10]+partV[11];
    float dt2 = partV[12]+partV[13]+partV[14]+partV[15];
    g_a1[bt] = dt1 / fmaxf(sqrtf(sq1), 1e-12f);
    g_a2[bt] = dt2 / fmaxf(sqrtf(sq2), 1e-12f);
  }

  if (t < TM1){
    if (tid < TWOF){
      float acc = sc_b1[tid];
      #pragma unroll 16
      for (int k = 0; k < TWOF; k++)
        acc = fmaf(g_W1T[k*TWOF + tid], msV[k], acc);
      hsV[tid] = fmaxf(acc, 0.f);
    }
    __syncthreads();
    if (warp < 3){
      float p = 0.f;
      #pragma unroll
      for (int q = 0; q < 4; q++)
        p += hsV[lane + 32*q] * __ldg(&sc_W2[warp*TWOF + lane + 32*q]);
      p = warp_sum(p);
      if (lane == 0) lgV[warp] = p + sc_b2[warp];
    }
    __syncthreads();
    if (tid == 0){
      int cp = g_cnt_pos[b*TM1 + t], cn = g_cnt_neg[b*TM1 + t];
      g_cnt_pos[b*TM1 + t] = 0;
      g_cnt_neg[b*TM1 + t] = 0;
      float pr = (float)cp * (1.0f/NI);
      float nr = (float)cn * (1.0f/NI);
      int lbl = (pr >= 0.6f) ? 0 : ((nr >= 0.6f) ? 1 : 2);
      float mx = fmaxf(lgV[0], fmaxf(lgV[1], lgV[2]));
      float lse = logf(expf(lgV[0]-mx) + expf(lgV[1]-mx) + expf(lgV[2]-mx)) + mx;
      g_sync[b*TM1 + t] = lse - lgV[lbl];
    }
  }

  // ---- release; globally last block does the loss ----
  __syncthreads();
  __threadfence();
  if (tid == 0) flags[1] = (atomicAdd(&g_done_all, 1) == NB*NT - 1);
  __syncthreads();
  if (!flags[1]) return;
  __threadfence();   // acquire
  if (tid == 0) g_done_all = 0;

  // ===== final loss =====
  float bm = *b_M;
  float acc = 0.f;
  if (tid < NT*NB){
    int t1 = tid & (NT-1), bb = tid >> 5;
    float a1v = g_a1[bb*NT + t1];
    float sum = 0.f, pos = 0.f;
    #pragma unroll 4
    for (int t2 = 0; t2 < NT; t2++){
      float sc = a1v + g_a2[bb*NT + t2] + bm;
      sc = fminf(fmaxf(sc, -10.f), 10.f);
      float tw = 1.0f / (fabsf((float)(t1 - t2)) + 1.0f);
      float w = expf(sc * tw);
      sum += w;
      if (t2 == t1) pos = w;
    }
    acc = logf(sum + 1e-8f) - logf(pos);
  }
  acc = warp_sum(acc);
  if (lane == 0) finA[warp] = acc;
  float sv = (tid < NB*TM1) ? g_sync[tid] : 0.f;
  sv = warp_sum(sv);
  if (lane == 0) finB[warp] = sv;
  __syncthreads();
  if (tid == 0){
    float lc = 0.f, ls = 0.f;
    #pragma unroll
    for (int w = 0; w < 8; w++){ lc += finA[w]; ls += finB[w]; }
    d_out[LOSS_OFF] = lc * (1.0f/(NT*NB)) + ls * (1.0f/(NB*TM1));
  }
}

// ---------------- launch ----------------
extern "C" void kernel_launch(void* const* d_in, const int* in_sizes, int n_in,
                              void* d_out, int out_size){
  const float* e_seq = (const float*)d_in[0];
  const float* Ws_w  = (const float*)d_in[2];
  const float* Ws_b  = (const float*)d_in[3];
  const float* Wiota = (const float*)d_in[4];
  const float* w_eta = (const float*)d_in[5];
  const float* w_M   = (const float*)d_in[6];
  const float* b_M   = (const float*)d_in[7];
  const float* sc_W1 = (const float*)d_in[8];
  const float* sc_b1 = (const float*)d_in[9];
  const float* sc_W2 = (const float*)d_in[10];
  const float* sc_b2 = (const float*)d_in[11];
  const int*  perms  = (const int*)d_in[12];
  const int*  cidx   = (const int*)d_in[13];
  float* out = (float*)d_out;

  k_main<<<dim3(NI/2, NB+1), 256>>>(e_seq, Ws_w, Ws_b, w_eta, cidx,
                                    Wiota, perms, sc_W1, out);
  k_msum<<<dim3(NB*NT, NSPLIT), 256>>>(w_M, sc_b1, sc_W2, sc_b2, b_M, out);
}